// round 1
// baseline (speedup 1.0000x reference)
#include <cuda_runtime.h>
#include <math.h>

#define BB 2048
#define MMOD 4
#define DD 256
#define CC 512
#define NROW (BB*MMOD)   // 8192

// Scratch (no allocations allowed) — ~25 MB total
__device__ float g_Z[NROW * DD];        // projected+LN'd features, [B,M,D] interleaved
__device__ float g_rnorm[NROW];         // 1/(||Z_row||+1e-6)
__device__ float g_Un[CC * DD];         // l2-normalized U
__device__ float g_OjZ[NROW * CC];      // O . Z  per (b,m,c)

// ---------------------------------------------------------------------------
// Tiled NT GEMM: C[r, c] = sum_k A[r, k] * Bm[c, k]   (A: lda=K, Bm: ldb=K)
// 64x64 tile, TK=16, 256 threads, 4x4 per thread.
// Epilogue: v = (acc + bias[c]) * (rowscale ? rowscale[r]*alpha : 1)
// Requires: M%64==0, N%64==0, K%16==0 (all true here).
// ---------------------------------------------------------------------------
__global__ void __launch_bounds__(256) gemm_nt(
    const float* __restrict__ A, const float* __restrict__ Bm,
    const float* __restrict__ bias, const float* __restrict__ rowscale,
    float alpha, float* __restrict__ C, int K, int ldc)
{
    __shared__ float As[64][17];
    __shared__ float Bs[64][17];
    const int tid = threadIdx.x;
    const int tx = tid & 15;          // 0..15 -> 4 output cols
    const int ty = tid >> 4;          // 0..15 -> 4 output rows
    const int row0 = blockIdx.y * 64;
    const int col0 = blockIdx.x * 64;
    const int lr = tid >> 2;          // 0..63 load row
    const int lk = (tid & 3) << 2;    // 0,4,8,12 load k (float4)

    float acc[4][4];
#pragma unroll
    for (int i = 0; i < 4; i++)
#pragma unroll
        for (int j = 0; j < 4; j++) acc[i][j] = 0.f;

    for (int k0 = 0; k0 < K; k0 += 16) {
        float4 av = *(const float4*)(A  + (size_t)(row0 + lr) * K + k0 + lk);
        float4 bv = *(const float4*)(Bm + (size_t)(col0 + lr) * K + k0 + lk);
        As[lr][lk + 0] = av.x; As[lr][lk + 1] = av.y;
        As[lr][lk + 2] = av.z; As[lr][lk + 3] = av.w;
        Bs[lr][lk + 0] = bv.x; Bs[lr][lk + 1] = bv.y;
        Bs[lr][lk + 2] = bv.z; Bs[lr][lk + 3] = bv.w;
        __syncthreads();
#pragma unroll
        for (int kk = 0; kk < 16; ++kk) {
            float a0 = As[ty * 4 + 0][kk], a1 = As[ty * 4 + 1][kk];
            float a2 = As[ty * 4 + 2][kk], a3 = As[ty * 4 + 3][kk];
            float b0 = Bs[tx * 4 + 0][kk], b1 = Bs[tx * 4 + 1][kk];
            float b2 = Bs[tx * 4 + 2][kk], b3 = Bs[tx * 4 + 3][kk];
            acc[0][0] += a0 * b0; acc[0][1] += a0 * b1; acc[0][2] += a0 * b2; acc[0][3] += a0 * b3;
            acc[1][0] += a1 * b0; acc[1][1] += a1 * b1; acc[1][2] += a1 * b2; acc[1][3] += a1 * b3;
            acc[2][0] += a2 * b0; acc[2][1] += a2 * b1; acc[2][2] += a2 * b2; acc[2][3] += a2 * b3;
            acc[3][0] += a3 * b0; acc[3][1] += a3 * b1; acc[3][2] += a3 * b2; acc[3][3] += a3 * b3;
        }
        __syncthreads();
    }

#pragma unroll
    for (int i = 0; i < 4; i++) {
        const int r = row0 + ty * 4 + i;
        const float rs = rowscale ? rowscale[r] * alpha : 1.f;
#pragma unroll
        for (int j = 0; j < 4; j++) {
            const int c = col0 + tx * 4 + j;
            float v = acc[i][j];
            if (bias) v += bias[c];
            v *= rs;
            C[(size_t)r * ldc + c] = v;
        }
    }
}

// ---------------------------------------------------------------------------
// LayerNorm + l2-norm factor per row of g_Z (8192 rows of 256). row%4 = modality.
// ---------------------------------------------------------------------------
__global__ void __launch_bounds__(256) ln_l2_kernel(
    const float* __restrict__ g0, const float* __restrict__ g1,
    const float* __restrict__ g2, const float* __restrict__ g3,
    const float* __restrict__ e0, const float* __restrict__ e1,
    const float* __restrict__ e2, const float* __restrict__ e3)
{
    const int row = blockIdx.x;
    const int t = threadIdx.x;
    float y = g_Z[(size_t)row * DD + t];
    float s = y, s2 = y * y;
#pragma unroll
    for (int o = 16; o > 0; o >>= 1) {
        s  += __shfl_xor_sync(0xffffffffu, s, o);
        s2 += __shfl_xor_sync(0xffffffffu, s2, o);
    }
    __shared__ float ws[8], ws2[8];
    const int w = t >> 5, ln = t & 31;
    if (ln == 0) { ws[w] = s; ws2[w] = s2; }
    __syncthreads();
    float tot = 0.f, tot2 = 0.f;
#pragma unroll
    for (int i = 0; i < 8; i++) { tot += ws[i]; tot2 += ws2[i]; }
    const float mu = tot * (1.f / DD);
    const float var = tot2 * (1.f / DD) - mu * mu;
    float z = (y - mu) * rsqrtf(var + 1e-5f);
    const int m = row & 3;
    const float* g = (m == 0) ? g0 : (m == 1) ? g1 : (m == 2) ? g2 : g3;
    const float* e = (m == 0) ? e0 : (m == 1) ? e1 : (m == 2) ? e2 : e3;
    z = z * g[t] + e[t];
    float q = z * z;
#pragma unroll
    for (int o = 16; o > 0; o >>= 1) q += __shfl_xor_sync(0xffffffffu, q, o);
    __syncthreads();
    if (ln == 0) ws[w] = q;
    __syncthreads();
    float n2 = 0.f;
#pragma unroll
    for (int i = 0; i < 8; i++) n2 += ws[i];
    g_Z[(size_t)row * DD + t] = z;
    if (t == 0) g_rnorm[row] = 1.f / (sqrtf(n2) + 1e-6f);
}

// ---------------------------------------------------------------------------
// Un = U / (||U|| + 1e-6), 512 rows of 256
// ---------------------------------------------------------------------------
__global__ void __launch_bounds__(256) un_kernel(const float* __restrict__ U)
{
    const int row = blockIdx.x;
    const int t = threadIdx.x;
    float u = U[(size_t)row * DD + t];
    float q = u * u;
#pragma unroll
    for (int o = 16; o > 0; o >>= 1) q += __shfl_xor_sync(0xffffffffu, q, o);
    __shared__ float ws[8];
    const int w = t >> 5, ln = t & 31;
    if (ln == 0) ws[w] = q;
    __syncthreads();
    float n2 = 0.f;
#pragma unroll
    for (int i = 0; i < 8; i++) n2 += ws[i];
    g_Un[(size_t)row * DD + t] = u / (sqrtf(n2) + 1e-6f);
}

// ---------------------------------------------------------------------------
// Softmax over M=4 + r, contrib, logits. One thread per (b,c).
// ---------------------------------------------------------------------------
__global__ void __launch_bounds__(256) finalize_kernel(
    const float* __restrict__ cls_bias, const float* __restrict__ sim,
    float* __restrict__ out_logits, float* __restrict__ out_r,
    float* __restrict__ out_contrib)
{
    const int idx = blockIdx.x * 256 + threadIdx.x;   // b*512 + c
    const int b = idx >> 9, c = idx & 511;
    float s[4], o[4];
#pragma unroll
    for (int m = 0; m < 4; m++) {
        const size_t off = (size_t)(b * 4 + m) * CC + c;
        s[m] = sim[off];
        o[m] = g_OjZ[off];
    }
    const float mx = fmaxf(fmaxf(s[0], s[1]), fmaxf(s[2], s[3]));
    float e[4], tot = 0.f;
#pragma unroll
    for (int m = 0; m < 4; m++) { e[m] = expf(s[m] - mx); tot += e[m]; }
    const float inv = 1.f / tot;
    float lg = 0.f;
#pragma unroll
    for (int m = 0; m < 4; m++) {
        const size_t off = (size_t)(b * 4 + m) * CC + c;
        const float r = e[m] * inv;
        out_r[off] = r;
        const float ct = o[m] * r;
        out_contrib[off] = ct;
        lg += ct;
    }
    out_logits[idx] = lg + cls_bias[c];
}

// ---------------------------------------------------------------------------
extern "C" void kernel_launch(void* const* d_in, const int* in_sizes, int n_in,
                              void* d_out, int out_size)
{
    const float *f[4], *W[4], *bi[4], *ga[4], *be[4];
    // Adaptive input parsing: dict order (f,W,b,g,be per modality) vs signature
    // order (f x4, then (W,b,g,be) x4). Distinguish via in_sizes[1]:
    // dict -> W_text = 256*1024 = 262144 ; signature -> f_image = 2097152.
    if (in_sizes[1] == 256 * 1024) {
        for (int m = 0; m < 4; m++) {
            f[m]  = (const float*)d_in[m * 5 + 0];
            W[m]  = (const float*)d_in[m * 5 + 1];
            bi[m] = (const float*)d_in[m * 5 + 2];
            ga[m] = (const float*)d_in[m * 5 + 3];
            be[m] = (const float*)d_in[m * 5 + 4];
        }
    } else {
        for (int m = 0; m < 4; m++) f[m] = (const float*)d_in[m];
        for (int m = 0; m < 4; m++) {
            W[m]  = (const float*)d_in[4 + m * 4 + 0];
            bi[m] = (const float*)d_in[4 + m * 4 + 1];
            ga[m] = (const float*)d_in[4 + m * 4 + 2];
            be[m] = (const float*)d_in[4 + m * 4 + 3];
        }
    }
    const float* U   = (const float*)d_in[20];
    const float* O   = (const float*)d_in[21];
    const float* cls = (const float*)d_in[22];

    float *Z, *Un, *OjZ, *rn;
    cudaGetSymbolAddress((void**)&Z,   g_Z);
    cudaGetSymbolAddress((void**)&Un,  g_Un);
    cudaGetSymbolAddress((void**)&OjZ, g_OjZ);
    cudaGetSymbolAddress((void**)&rn,  g_rnorm);

    // Output layout (reference return order): logits | r | sim | contrib
    float* out         = (float*)d_out;
    float* out_logits  = out;
    float* out_r       = out + (size_t)BB * CC;
    float* out_sim     = out_r + (size_t)BB * MMOD * CC;
    float* out_contrib = out_sim + (size_t)BB * MMOD * CC;

    const int Kd[4] = {1024, 1024, 512, 256};   // text, image, audio, tab

    un_kernel<<<CC, 256>>>(U);

    // Projections: Y = f_m @ W_m^T + b_m, written into interleaved [B,M,D]
    for (int m = 0; m < 4; m++) {
        dim3 grid(DD / 64, BB / 64);
        gemm_nt<<<grid, 256>>>(f[m], W[m], bi[m], nullptr, 1.f,
                               Z + m * DD, Kd[m], MMOD * DD);
    }

    ln_l2_kernel<<<NROW, 256>>>(ga[0], ga[1], ga[2], ga[3],
                                be[0], be[1], be[2], be[3]);

    {
        dim3 grid(CC / 64, NROW / 64);
        // sim = (Z @ Un^T) * rnorm[row] / tau  -> straight into d_out sim region
        gemm_nt<<<grid, 256>>>(Z, Un, nullptr, rn, 1.f / 0.07f,
                               out_sim, DD, CC);
        // OjZ = Z @ O^T
        gemm_nt<<<grid, 256>>>(Z, O, nullptr, nullptr, 1.f,
                               OjZ, DD, CC);
    }

    finalize_kernel<<<(BB * CC) / 256, 256>>>(cls, out_sim, out_logits,
                                              out_r, out_contrib);
}

// round 2
// speedup vs baseline: 2.8370x; 2.8370x over previous
#include <cuda_runtime.h>
#include <cuda_bf16.h>
#include <math.h>

#define BB 2048
#define DD 256
#define CC 512
#define NROW 8192
#define INVTAU (1.0f/0.07f)

#define FTOT 5767168   // 2048*(1024+1024+512+256)
#define WTOT 720896    // 256*(1024+1024+512+256)

// ---------------- scratch (no allocations allowed) ----------------
__device__ __nv_bfloat16 g_fhi[FTOT], g_flo[FTOT];
__device__ __nv_bfloat16 g_whi[WTOT], g_wlo[WTOT];
__device__ float         g_Zpart[2 * NROW * DD];        // split-K partials
__device__ __nv_bfloat16 g_Zhi[NROW * DD], g_Zlo[NROW * DD];
__device__ __nv_bfloat16 g_Bhi[1024 * DD], g_Blo[1024 * DD]; // rows 0-511: Un, 512-1023: O
__device__ float         g_OjZ[NROW * CC];
__device__ float         g_rnorm[NROW];

__device__ __forceinline__ void split2(float x, __nv_bfloat16& h, __nv_bfloat16& l) {
    h = __float2bfloat16_rn(x);
    l = __float2bfloat16_rn(x - __bfloat162float(h));
}

#define MMA_BF16(d, a, b) asm volatile( \
    "mma.sync.aligned.m16n8k16.row.col.f32.bf16.bf16.f32 " \
    "{%0,%1,%2,%3}, {%4,%5,%6,%7}, {%8,%9}, {%0,%1,%2,%3};\n" \
    : "+f"((d)[0]), "+f"((d)[1]), "+f"((d)[2]), "+f"((d)[3]) \
    : "r"((a)[0]), "r"((a)[1]), "r"((a)[2]), "r"((a)[3]), "r"((b)[0]), "r"((b)[1]))

// ---------------------------------------------------------------------------
// fp32 -> bf16 hi/lo conversion for f_* and W_* (one fused launch)
// ---------------------------------------------------------------------------
__global__ void __launch_bounds__(256) cvt_fw(
    const float* f0, const float* f1, const float* f2, const float* f3,
    const float* w0, const float* w1, const float* w2, const float* w3)
{
    const int cum[8] = {2048, 4096, 5120, 5632, 5888, 6144, 6272, 6336};
    int blk = blockIdx.x, seg = 0;
    while (blk >= cum[seg]) seg++;
    int lb = blk - (seg ? cum[seg - 1] : 0);
    const float* src;
    __nv_bfloat16 *hi, *lo;
    switch (seg) {
        case 0: src = f0; hi = g_fhi;           lo = g_flo;           break;
        case 1: src = f1; hi = g_fhi + 2097152; lo = g_flo + 2097152; break;
        case 2: src = f2; hi = g_fhi + 4194304; lo = g_flo + 4194304; break;
        case 3: src = f3; hi = g_fhi + 5242880; lo = g_flo + 5242880; break;
        case 4: src = w0; hi = g_whi;           lo = g_wlo;           break;
        case 5: src = w1; hi = g_whi + 262144;  lo = g_wlo + 262144;  break;
        case 6: src = w2; hi = g_whi + 524288;  lo = g_wlo + 524288;  break;
        default:src = w3; hi = g_whi + 655360;  lo = g_wlo + 655360;  break;
    }
    long base = (long)lb * 1024 + threadIdx.x * 4;
    float4 v = *(const float4*)(src + base);
    __nv_bfloat16 h0, h1, h2, h3, l0, l1, l2, l3;
    split2(v.x, h0, l0); split2(v.y, h1, l1);
    split2(v.z, h2, l2); split2(v.w, h3, l3);
    *(__nv_bfloat162*)(hi + base)     = __halves2bfloat162(h0, h1);
    *(__nv_bfloat162*)(hi + base + 2) = __halves2bfloat162(h2, h3);
    *(__nv_bfloat162*)(lo + base)     = __halves2bfloat162(l0, l1);
    *(__nv_bfloat162*)(lo + base + 2) = __halves2bfloat162(l2, l3);
}

// ---------------------------------------------------------------------------
// Un = l2norm(U) rows 0-511; O copied rows 512-1023; -> bf16 hi/lo
// ---------------------------------------------------------------------------
__global__ void __launch_bounds__(256) normcat_kernel(const float* __restrict__ U,
                                                      const float* __restrict__ O)
{
    const int rr = blockIdx.x, t = threadIdx.x;
    __shared__ float ws[8];
    float v;
    if (rr < 512) {
        float u = U[(long)rr * DD + t];
        float q = u * u;
#pragma unroll
        for (int o = 16; o > 0; o >>= 1) q += __shfl_xor_sync(0xffffffffu, q, o);
        if ((t & 31) == 0) ws[t >> 5] = q;
        __syncthreads();
        float n2 = 0.f;
#pragma unroll
        for (int i = 0; i < 8; i++) n2 += ws[i];
        v = u / (sqrtf(n2) + 1e-6f);
    } else {
        v = O[(long)(rr - 512) * DD + t];
    }
    __nv_bfloat16 h, l; split2(v, h, l);
    g_Bhi[(long)rr * DD + t] = h;
    g_Blo[(long)rr * DD + t] = l;
}

// ---------------------------------------------------------------------------
// bf16 hi/lo tensor-core GEMM. CTA tile 128x128, kTile 32, 256 thr, 8 warps.
// mode 0: projections. grid (2, 16, 8): z = modality*2 + ksplit. C += into partials.
// mode 1: head GEMM Z[8192,256] @ Bcat^T[256,1024]. grid (8, 64, 1).
// ---------------------------------------------------------------------------
__global__ void __launch_bounds__(256, 1) gemm_bf16(int mode, float* out_sim)
{
    extern __shared__ __nv_bfloat16 smbuf[];   // 2 stages * (Ahi|Alo|Bhi|Blo) * 128*40
    const int tid = threadIdx.x;

    const __nv_bfloat16 *Ahi, *Alo, *Bhi_, *Blo_;
    int lda, ldb, nkt;
    float* Cp = nullptr;
    if (mode == 0) {
        const long foff[4] = {0, 2097152, 4194304, 5242880};
        const long woff[4] = {0, 262144, 524288, 655360};
        const int  Km[4]   = {1024, 1024, 512, 256};
        const int md = blockIdx.z >> 1, s = blockIdx.z & 1;
        const int Keff = Km[md] >> 1;
        lda = ldb = Km[md];
        Ahi  = g_fhi + foff[md] + (long)s * Keff;
        Alo  = g_flo + foff[md] + (long)s * Keff;
        Bhi_ = g_whi + woff[md] + (long)s * Keff;
        Blo_ = g_wlo + woff[md] + (long)s * Keff;
        Cp   = g_Zpart + (long)s * NROW * DD + md * DD;
        nkt = Keff >> 5;
    } else {
        lda = ldb = DD;
        Ahi = g_Zhi; Alo = g_Zlo; Bhi_ = g_Bhi; Blo_ = g_Blo;
        nkt = DD >> 5;
    }
    const int row0 = blockIdx.y * 128;
    const int col0 = blockIdx.x * 128;
    Ahi  += (long)row0 * lda;  Alo  += (long)row0 * lda;
    Bhi_ += (long)col0 * ldb;  Blo_ += (long)col0 * ldb;

    const int wid = tid >> 5, lane = tid & 31;
    const int wm = wid >> 2, wn = wid & 3;    // warp grid 2x4, warp tile 64x32
    const int g = lane >> 2, t4 = lane & 3;

    // ---- prologue: load stage 0 ----
    {
#pragma unroll
        for (int i = 0; i < 8; i++) {
            const int arr = i >> 1;
            const int row = ((i & 1) << 6) + (tid >> 2);
            const int qc = tid & 3;
            const __nv_bfloat16* src = arr == 0 ? Ahi : arr == 1 ? Alo : arr == 2 ? Bhi_ : Blo_;
            const int ld = (arr < 2) ? lda : ldb;
            uint4 v = *(const uint4*)(src + (long)row * ld + qc * 8);
            *(uint4*)(smbuf + arr * 5120 + row * 40 + qc * 8) = v;
        }
    }
    __syncthreads();

    float acc[4][4][4];
#pragma unroll
    for (int im = 0; im < 4; im++)
#pragma unroll
        for (int jn = 0; jn < 4; jn++)
#pragma unroll
            for (int q = 0; q < 4; q++) acc[im][jn][q] = 0.f;

    for (int kt = 0; kt < nkt; kt++) {
        uint4 pref[8];
        const bool hasNext = (kt + 1 < nkt);
        if (hasNext) {
            const int k0 = (kt + 1) << 5;
#pragma unroll
            for (int i = 0; i < 8; i++) {
                const int arr = i >> 1;
                const int row = ((i & 1) << 6) + (tid >> 2);
                const int qc = tid & 3;
                const __nv_bfloat16* src = arr == 0 ? Ahi : arr == 1 ? Alo : arr == 2 ? Bhi_ : Blo_;
                const int ld = (arr < 2) ? lda : ldb;
                pref[i] = *(const uint4*)(src + (long)row * ld + k0 + qc * 8);
            }
        }
        const __nv_bfloat16* sb = smbuf + (kt & 1) * 20480;
#pragma unroll
        for (int ks = 0; ks < 32; ks += 16) {
            unsigned ahi[4][4], alo[4][4], bhi[4][2], blo[4][2];
#pragma unroll
            for (int im = 0; im < 4; im++) {
                const int r0 = wm * 64 + im * 16 + g;
                const int o = r0 * 40 + ks + 2 * t4;
                ahi[im][0] = *(const unsigned*)(sb + o);
                ahi[im][1] = *(const unsigned*)(sb + o + 8 * 40);
                ahi[im][2] = *(const unsigned*)(sb + o + 8);
                ahi[im][3] = *(const unsigned*)(sb + o + 8 * 40 + 8);
                alo[im][0] = *(const unsigned*)(sb + 5120 + o);
                alo[im][1] = *(const unsigned*)(sb + 5120 + o + 8 * 40);
                alo[im][2] = *(const unsigned*)(sb + 5120 + o + 8);
                alo[im][3] = *(const unsigned*)(sb + 5120 + o + 8 * 40 + 8);
            }
#pragma unroll
            for (int jn = 0; jn < 4; jn++) {
                const int n0 = wn * 32 + jn * 8 + g;
                const int o = n0 * 40 + ks + 2 * t4;
                bhi[jn][0] = *(const unsigned*)(sb + 10240 + o);
                bhi[jn][1] = *(const unsigned*)(sb + 10240 + o + 8);
                blo[jn][0] = *(const unsigned*)(sb + 15360 + o);
                blo[jn][1] = *(const unsigned*)(sb + 15360 + o + 8);
            }
#pragma unroll
            for (int im = 0; im < 4; im++)
#pragma unroll
                for (int jn = 0; jn < 4; jn++) {
                    MMA_BF16(acc[im][jn], ahi[im], bhi[jn]);
                    MMA_BF16(acc[im][jn], ahi[im], blo[jn]);
                    MMA_BF16(acc[im][jn], alo[im], bhi[jn]);
                }
        }
        if (hasNext) {
            const int st = (kt + 1) & 1;
#pragma unroll
            for (int i = 0; i < 8; i++) {
                const int arr = i >> 1;
                const int row = ((i & 1) << 6) + (tid >> 2);
                const int qc = tid & 3;
                *(uint4*)(smbuf + st * 20480 + arr * 5120 + row * 40 + qc * 8) = pref[i];
            }
        }
        __syncthreads();
    }

    // ---- epilogue ----
    if (mode == 0) {
#pragma unroll
        for (int im = 0; im < 4; im++) {
            const int rbase = row0 + wm * 64 + im * 16 + g;
#pragma unroll
            for (int h = 0; h < 2; h++) {
                const long r = rbase + h * 8;
#pragma unroll
                for (int jn = 0; jn < 4; jn++) {
                    const int c = col0 + wn * 32 + jn * 8 + 2 * t4;
                    float2 v = make_float2(acc[im][jn][h * 2], acc[im][jn][h * 2 + 1]);
                    *(float2*)(Cp + r * 1024 + c) = v;  // ldc = 4*DD (interleaved B,M)
                }
            }
        }
    } else {
#pragma unroll
        for (int im = 0; im < 4; im++) {
            const int rbase = row0 + wm * 64 + im * 16 + g;
#pragma unroll
            for (int h = 0; h < 2; h++) {
                const long r = rbase + h * 8;
                const float rs = g_rnorm[r] * INVTAU;
#pragma unroll
                for (int jn = 0; jn < 4; jn++) {
                    const int c = col0 + wn * 32 + jn * 8 + 2 * t4;
                    float2 v = make_float2(acc[im][jn][h * 2], acc[im][jn][h * 2 + 1]);
                    if (c < 512) {
                        v.x *= rs; v.y *= rs;
                        *(float2*)(out_sim + r * 512 + c) = v;
                    } else {
                        *(float2*)(g_OjZ + r * 512 + (c - 512)) = v;
                    }
                }
            }
        }
    }
}

// ---------------------------------------------------------------------------
// Sum split-K partials + bias, LayerNorm, l2-factor; emit bf16 hi/lo of Z
// ---------------------------------------------------------------------------
__global__ void __launch_bounds__(256) ln_kernel(
    const float* b0, const float* b1, const float* b2, const float* b3,
    const float* g0, const float* g1, const float* g2, const float* g3,
    const float* e0, const float* e1, const float* e2, const float* e3)
{
    const int row = blockIdx.x, t = threadIdx.x, m = row & 3;
    const float* bi = m == 0 ? b0 : m == 1 ? b1 : m == 2 ? b2 : b3;
    const float* gg = m == 0 ? g0 : m == 1 ? g1 : m == 2 ? g2 : g3;
    const float* ee = m == 0 ? e0 : m == 1 ? e1 : m == 2 ? e2 : e3;
    const long off = (long)row * DD + t;
    float y = g_Zpart[off] + g_Zpart[(long)NROW * DD + off] + bi[t];

    float s = y, s2 = y * y;
#pragma unroll
    for (int o = 16; o > 0; o >>= 1) {
        s  += __shfl_xor_sync(0xffffffffu, s, o);
        s2 += __shfl_xor_sync(0xffffffffu, s2, o);
    }
    __shared__ float ws[8], ws2[8];
    const int w = t >> 5, ln = t & 31;
    if (ln == 0) { ws[w] = s; ws2[w] = s2; }
    __syncthreads();
    float tot = 0.f, tot2 = 0.f;
#pragma unroll
    for (int i = 0; i < 8; i++) { tot += ws[i]; tot2 += ws2[i]; }
    const float mu = tot * (1.f / DD);
    const float var = tot2 * (1.f / DD) - mu * mu;
    float z = (y - mu) * rsqrtf(var + 1e-5f) * gg[t] + ee[t];

    float q = z * z;
#pragma unroll
    for (int o = 16; o > 0; o >>= 1) q += __shfl_xor_sync(0xffffffffu, q, o);
    __syncthreads();
    if (ln == 0) ws[w] = q;
    __syncthreads();
    float n2 = 0.f;
#pragma unroll
    for (int i = 0; i < 8; i++) n2 += ws[i];

    __nv_bfloat16 h, l; split2(z, h, l);
    g_Zhi[off] = h; g_Zlo[off] = l;
    if (t == 0) g_rnorm[row] = 1.f / (sqrtf(n2) + 1e-6f);
}

// ---------------------------------------------------------------------------
// Softmax over M=4 + r, contrib, logits. One thread per (b,c).
// ---------------------------------------------------------------------------
__global__ void __launch_bounds__(256) finalize_kernel(
    const float* __restrict__ cls_bias, const float* __restrict__ sim,
    float* __restrict__ out_logits, float* __restrict__ out_r,
    float* __restrict__ out_contrib)
{
    const int idx = blockIdx.x * 256 + threadIdx.x;
    const int b = idx >> 9, c = idx & 511;
    float s[4], o[4];
#pragma unroll
    for (int m = 0; m < 4; m++) {
        const long off = (long)(b * 4 + m) * CC + c;
        s[m] = sim[off];
        o[m] = g_OjZ[off];
    }
    const float mx = fmaxf(fmaxf(s[0], s[1]), fmaxf(s[2], s[3]));
    float e[4], tot = 0.f;
#pragma unroll
    for (int m = 0; m < 4; m++) { e[m] = expf(s[m] - mx); tot += e[m]; }
    const float inv = 1.f / tot;
    float lg = 0.f;
#pragma unroll
    for (int m = 0; m < 4; m++) {
        const long off = (long)(b * 4 + m) * CC + c;
        const float r = e[m] * inv;
        out_r[off] = r;
        const float ct = o[m] * r;
        out_contrib[off] = ct;
        lg += ct;
    }
    out_logits[idx] = lg + cls_bias[c];
}

// ---------------------------------------------------------------------------
extern "C" void kernel_launch(void* const* d_in, const int* in_sizes, int n_in,
                              void* d_out, int out_size)
{
    const float *f[4], *W[4], *bi[4], *ga[4], *be[4];
    if (in_sizes[1] == 256 * 1024) {   // dict order: (f,W,b,g,be) per modality
        for (int m = 0; m < 4; m++) {
            f[m]  = (const float*)d_in[m * 5 + 0];
            W[m]  = (const float*)d_in[m * 5 + 1];
            bi[m] = (const float*)d_in[m * 5 + 2];
            ga[m] = (const float*)d_in[m * 5 + 3];
            be[m] = (const float*)d_in[m * 5 + 4];
        }
    } else {                            // signature order
        for (int m = 0; m < 4; m++) f[m] = (const float*)d_in[m];
        for (int m = 0; m < 4; m++) {
            W[m]  = (const float*)d_in[4 + m * 4 + 0];
            bi[m] = (const float*)d_in[4 + m * 4 + 1];
            ga[m] = (const float*)d_in[4 + m * 4 + 2];
            be[m] = (const float*)d_in[4 + m * 4 + 3];
        }
    }
    const float* U   = (const float*)d_in[20];
    const float* O   = (const float*)d_in[21];
    const float* cls = (const float*)d_in[22];

    float* out         = (float*)d_out;
    float* out_logits  = out;
    float* out_r       = out + (long)BB * CC;
    float* out_sim     = out_r + (long)NROW * CC;
    float* out_contrib = out_sim + (long)NROW * CC;

    const int SMEM_BYTES = 2 * 4 * 128 * 40 * 2;   // 81920
    cudaFuncSetAttribute(gemm_bf16, cudaFuncAttributeMaxDynamicSharedMemorySize, SMEM_BYTES);

    cvt_fw<<<6336, 256>>>(f[0], f[1], f[2], f[3], W[0], W[1], W[2], W[3]);
    normcat_kernel<<<1024, 256>>>(U, O);

    // projections: 4 modalities x 2-way K-split -> fp32 partials
    gemm_bf16<<<dim3(2, 16, 8), 256, SMEM_BYTES>>>(0, nullptr);

    ln_kernel<<<NROW, 256>>>(bi[0], bi[1], bi[2], bi[3],
                             ga[0], ga[1], ga[2], ga[3],
                             be[0], be[1], be[2], be[3]);

    // head GEMM: sim (cols 0-511, scaled) + OjZ (cols 512-1023)
    gemm_bf16<<<dim3(8, 64, 1), 256, SMEM_BYTES>>>(1, out_sim);

    finalize_kernel<<<(BB * CC) / 256, 256>>>(cls, out_sim, out_logits,
                                              out_r, out_contrib);
}